// round 11
// baseline (speedup 1.0000x reference)
#include <cuda_runtime.h>
#include <cuda_bf16.h>
#include <cstdint>

// Problem dims
#define B_    256
#define T_    100
#define FIN   784
#define FHID  500
#define FOUT  10
#define NTOK  25600   // B_*T_

// Neuron constants
#define EMF  0.7788007830714049f
#define A1F  1.1466802242428472f
#define A2F  -0.2865047968601901f

typedef __nv_bfloat16 bf16;

// ---------------------------------------------------------------------------
// Scratch (device globals; no allocation allowed)
// ---------------------------------------------------------------------------
__device__ float g_ann [NTOK * 1000];   // [n,1000] fp32
__device__ float g_cur2[NTOK * FHID];   // [n,500]
__device__ float g_psp3[NTOK * FHID];   // [n,500]
__device__ float g_cur3[NTOK * FOUT];   // [n,10]
// bf16x3 split operand planes (zero-padded to tile multiples)
__device__ bf16 g_w1p[3][1024 * 800];
__device__ bf16 g_w2p[3][512 * 512];
__device__ bf16 g_xp [3][NTOK * 800];
__device__ bf16 g_p2p[3][NTOK * 512];

// ---------------------------------------------------------------------------
// MMA helpers (baseline PTX, valid on plain sm_103 target)
// ---------------------------------------------------------------------------
__device__ __forceinline__ uint32_t smem_u32(const void* p) {
    uint32_t a;
    asm("{ .reg .u64 t; cvta.to.shared.u64 t, %1; cvt.u32.u64 %0, t; }"
        : "=r"(a) : "l"(p));
    return a;
}
__device__ __forceinline__ void ldsm4(uint32_t* r, uint32_t addr) {
    asm volatile("ldmatrix.sync.aligned.m8n8.x4.shared.b16 {%0,%1,%2,%3}, [%4];"
        : "=r"(r[0]), "=r"(r[1]), "=r"(r[2]), "=r"(r[3]) : "r"(addr));
}
__device__ __forceinline__ void mma_bf16(float* d, const uint32_t* a, const uint32_t* b) {
    asm volatile("mma.sync.aligned.m16n8k16.row.col.f32.bf16.bf16.f32 "
        "{%0,%1,%2,%3}, {%4,%5,%6,%7}, {%8,%9}, {%0,%1,%2,%3};"
        : "+f"(d[0]), "+f"(d[1]), "+f"(d[2]), "+f"(d[3])
        : "r"(a[0]), "r"(a[1]), "r"(a[2]), "r"(a[3]), "r"(b[0]), "r"(b[1]));
}
#define CP16(dst, src) \
    asm volatile("cp.async.cg.shared.global [%0], [%1], 16;" :: "r"(dst), "l"(src))
#define CP_COMMIT() asm volatile("cp.async.commit_group;" ::: "memory")
#define CP_WAIT0()  asm volatile("cp.async.wait_group 0;" ::: "memory")

// ---------------------------------------------------------------------------
// bf16x3 split: residual <= ~2^-25 |x|, full fp32 exponent range
// ---------------------------------------------------------------------------
__device__ __forceinline__ void split3(float x, bf16& b0, bf16& b1, bf16& b2) {
    b0 = __float2bfloat16_rn(x);
    float r1 = __fsub_rn(x, __bfloat162float(b0));
    b1 = __float2bfloat16_rn(r1);
    b2 = __float2bfloat16_rn(__fsub_rn(r1, __bfloat162float(b1)));
}

// ---------------------------------------------------------------------------
// Weight pre-split (+ zero padding)
// ---------------------------------------------------------------------------
template<int SEL>
__global__ __launch_bounds__(256)
void split_w_kernel(const float* __restrict__ W) {
    constexpr int O  = SEL ? FHID : 1000;
    constexpr int K  = SEL ? FHID : FIN;
    constexpr int OP = SEL ? 512  : 1024;
    constexpr int KP = SEL ? 512  : 800;
    int i = blockIdx.x * 256 + threadIdx.x;
    if (i >= OP * KP) return;
    int o = i / KP, k = i - o * KP;
    float v = (o < O && k < K) ? W[o * K + k] : 0.f;
    bf16 b0, b1, b2;
    split3(v, b0, b1, b2);
    if (SEL) { g_w2p[0][i] = b0; g_w2p[1][i] = b1; g_w2p[2][i] = b2; }
    else     { g_w1p[0][i] = b0; g_w1p[1][i] = b1; g_w1p[2][i] = b2; }
}

// ---------------------------------------------------------------------------
// Inputs [b,784,t] -> transpose + split3 -> g_xp planes [n, 800]
// ---------------------------------------------------------------------------
__global__ __launch_bounds__(256)
void transpose_split_inputs(const float* __restrict__ inp) {
    __shared__ float s[32][105];
    const int b  = blockIdx.y;
    const int k0 = blockIdx.x * 32;
    for (int i = threadIdx.x; i < 3200; i += 256) {
        int kk = i / 100, t = i - kk * 100;
        int k = k0 + kk;
        s[kk][t] = (k < FIN) ? inp[b * (FIN * T_) + k * T_ + t] : 0.f;
    }
    __syncthreads();
    for (int i = threadIdx.x; i < 3200; i += 256) {
        int t = i >> 5, kk = i & 31;
        bf16 b0, b1, b2;
        split3(s[kk][t], b0, b1, b2);
        int idx = (b * T_ + t) * 800 + k0 + kk;
        g_xp[0][idx] = b0;
        g_xp[1][idx] = b1;
        g_xp[2][idx] = b2;
    }
}

// ---------------------------------------------------------------------------
// GEMM on HMMA, bf16x3 split, chunked RN accumulation.
// CTA 128(o) x 128(n), BK=32, 8 warps, warp tile 64x32 (2x4 warp grid).
// One CTA per SM; big warp N-tile halves LDSM traffic per MMA (LDS-bound fix).
// smem: A 2buf x 3pl x 128 x 80B = 61440; B same = 61440; total 122880.
// ---------------------------------------------------------------------------
template<int SEL>  // 0: O=1000,KP=800, RELU, Y=g_ann; 1: O=500,KP=512, Y=g_cur2
__global__ __launch_bounds__(256, 1)
void gemm_b3(const float* __restrict__ bias) {
    constexpr int O   = SEL ? FHID : 1000;
    constexpr int KP  = SEL ? 512  : 800;
    constexpr int NCH = KP / 32;
    const bf16* __restrict__ A0 = SEL ? g_w2p[0] : g_w1p[0];
    const bf16* __restrict__ A1 = SEL ? g_w2p[1] : g_w1p[1];
    const bf16* __restrict__ A2 = SEL ? g_w2p[2] : g_w1p[2];
    const bf16* __restrict__ B0 = SEL ? g_p2p[0] : g_xp[0];
    const bf16* __restrict__ B1 = SEL ? g_p2p[1] : g_xp[1];
    const bf16* __restrict__ B2 = SEL ? g_p2p[2] : g_xp[2];
    float* __restrict__ Y = SEL ? g_cur2 : g_ann;

    extern __shared__ __align__(16) char smem[];
    const uint32_t sbase = smem_u32(smem);
    const uint32_t sbB   = sbase + 61440;

    const int tid  = threadIdx.x;
    const int lane = tid & 31;
    const int wid  = tid >> 5;
    const int warp_o = wid >> 2;   // 0..1 (64 o-rows each)
    const int warp_n = wid & 3;    // 0..3 (32 n-cols each)
    const int o0 = blockIdx.x * 128;
    const int n0 = blockIdx.y * 128;

    // loaders (A and B symmetric): r = tid>>1 (0..127), kh = (tid&1)*16
    const int r  = tid >> 1;
    const int kh = (tid & 1) * 16;
    const uint32_t sts_a = sbase + r * 80 + kh * 2;   // + buf*30720 + pl*10240
    const uint32_t sts_b = sbB   + r * 80 + kh * 2;
    const bf16* ga[3] = { A0 + (o0 + r) * KP + kh, A1 + (o0 + r) * KP + kh,
                          A2 + (o0 + r) * KP + kh };
    const bf16* gb[3] = { B0 + (n0 + r) * KP + kh, B1 + (n0 + r) * KP + kh,
                          B2 + (n0 + r) * KP + kh };

    float accT[4][4][4];   // running total (RN-folded), warp tile 64x32
    #pragma unroll
    for (int mt = 0; mt < 4; mt++)
        #pragma unroll
        for (int nt = 0; nt < 4; nt++)
            #pragma unroll
            for (int i = 0; i < 4; i++) accT[mt][nt][i] = 0.f;

    auto load_chunk = [&](int c, int buf) {
        const int ko = c * 32;
        #pragma unroll
        for (int pl = 0; pl < 3; pl++) {
            const uint32_t da = sts_a + buf * 30720 + pl * 10240;
            CP16(da,      ga[pl] + ko);
            CP16(da + 16, ga[pl] + ko + 8);
            const uint32_t db = sts_b + buf * 30720 + pl * 10240;
            CP16(db,      gb[pl] + ko);
            CP16(db + 16, gb[pl] + ko + 8);
        }
    };

    // ldmatrix lane addressing (80B pitch, conflict-free)
    const uint32_t a_lane = (uint32_t)((lane & 15) * 80 + (lane >> 4) * 16);
    // B x4 over a 16-row block: lanes 0-7 n0-7/k0-7, 8-15 n0-7/k8-15,
    //                           16-23 n8-15/k0-7, 24-31 n8-15/k8-15
    const uint32_t b_lane = (uint32_t)((lane & 7) * 80 + ((lane >> 3) & 1) * 16 + (lane >> 4) * 640);
    const uint32_t abase0 = sbase + warp_o * 5120 + a_lane;   // 64 rows * 80B
    const uint32_t bbase0 = sbB + warp_n * 2560 + b_lane;     // 32 rows * 80B

    load_chunk(0, 0);
    CP_COMMIT();
    CP_WAIT0();
    __syncthreads();

    for (int c = 0; c < NCH; c++) {
        const int buf = c & 1;
        if (c + 1 < NCH) { load_chunk(c + 1, buf ^ 1); CP_COMMIT(); }

        float accC[4][4][4];   // fresh per-chunk accumulator (all 6 products)
        #pragma unroll
        for (int mt = 0; mt < 4; mt++)
            #pragma unroll
            for (int nt = 0; nt < 4; nt++)
                #pragma unroll
                for (int i = 0; i < 4; i++) accC[mt][nt][i] = 0.f;

        #pragma unroll
        for (int ks = 0; ks < 2; ks++) {
            // B fragments: 2 ldsm4 per plane (n-halves of 16), 3 planes
            uint32_t bfr[3][2][4];
            const uint32_t bb = bbase0 + buf * 30720 + ks * 32;
            #pragma unroll
            for (int p = 0; p < 3; p++) {
                ldsm4(bfr[p][0], bb + p * 10240);
                ldsm4(bfr[p][1], bb + p * 10240 + 1280);
            }

            const uint32_t ab = abase0 + buf * 30720 + ks * 32;
            uint32_t af[4][4];
            // ---- A plane 0: products with B planes 0,1,2 ----
            #pragma unroll
            for (int mt = 0; mt < 4; mt++) ldsm4(af[mt], ab + mt * 1280);
            #pragma unroll
            for (int pb = 0; pb < 3; pb++)
                #pragma unroll
                for (int mt = 0; mt < 4; mt++)
                    #pragma unroll
                    for (int nt = 0; nt < 4; nt++)
                        mma_bf16(accC[mt][nt], af[mt], &bfr[pb][nt >> 1][(nt & 1) * 2]);
            // ---- A plane 1: products with B planes 0,1 ----
            #pragma unroll
            for (int mt = 0; mt < 4; mt++) ldsm4(af[mt], ab + 10240 + mt * 1280);
            #pragma unroll
            for (int pb = 0; pb < 2; pb++)
                #pragma unroll
                for (int mt = 0; mt < 4; mt++)
                    #pragma unroll
                    for (int nt = 0; nt < 4; nt++)
                        mma_bf16(accC[mt][nt], af[mt], &bfr[pb][nt >> 1][(nt & 1) * 2]);
            // ---- A plane 2: product with B plane 0 ----
            #pragma unroll
            for (int mt = 0; mt < 4; mt++) ldsm4(af[mt], ab + 20480 + mt * 1280);
            #pragma unroll
            for (int mt = 0; mt < 4; mt++)
                #pragma unroll
                for (int nt = 0; nt < 4; nt++)
                    mma_bf16(accC[mt][nt], af[mt], &bfr[0][nt >> 1][(nt & 1) * 2]);
        }

        // fold chunk into running total with IEEE-RN adds
        #pragma unroll
        for (int mt = 0; mt < 4; mt++)
            #pragma unroll
            for (int nt = 0; nt < 4; nt++)
                #pragma unroll
                for (int i = 0; i < 4; i++)
                    accT[mt][nt][i] = __fadd_rn(accT[mt][nt][i], accC[mt][nt][i]);

        if (c + 1 < NCH) CP_WAIT0();
        __syncthreads();
    }

    // ---- epilogue: transpose through smem, coalesced fp32 writes ----
    float* es = reinterpret_cast<float*>(smem);   // [128][132]
    #pragma unroll
    for (int mt = 0; mt < 4; mt++)
        #pragma unroll
        for (int nt = 0; nt < 4; nt++)
            #pragma unroll
            for (int i = 0; i < 4; i++) {
                int ol = warp_o * 64 + mt * 16 + (lane >> 2) + 8 * (i >> 1);
                int nl = warp_n * 32 + nt * 8 + 2 * (lane & 3) + (i & 1);
                es[nl * 132 + ol] = accT[mt][nt][i];
            }
    __syncthreads();
    for (int it = tid; it < 128 * 32; it += 256) {
        int nl = it >> 5;
        int c4 = (it & 31) * 4;
        int o  = o0 + c4;
        if (o < O) {
            float4 v  = *reinterpret_cast<const float4*>(&es[nl * 132 + c4]);
            float4 bv = *reinterpret_cast<const float4*>(&bias[o]);
            v.x = __fadd_rn(v.x, bv.x);
            v.y = __fadd_rn(v.y, bv.y);
            v.z = __fadd_rn(v.z, bv.z);
            v.w = __fadd_rn(v.w, bv.w);
            if (!SEL) {
                v.x = fmaxf(v.x, 0.f); v.y = fmaxf(v.y, 0.f);
                v.z = fmaxf(v.z, 0.f); v.w = fmaxf(v.w, 0.f);
            }
            *reinterpret_cast<float4*>(&Y[(n0 + nl) * O + o]) = v;
        }
    }
}

// ---------------------------------------------------------------------------
// Threefry2x32-20, key=(0,42); partitionable path (verified bit-exact)
// ---------------------------------------------------------------------------
__device__ __forceinline__ unsigned rotl32(unsigned x, int r) {
    return (x << r) | (x >> (32 - r));
}
__device__ __forceinline__ void threefry2x32_k42(unsigned c0, unsigned c1,
                                                 unsigned& o0, unsigned& o1) {
    const unsigned k0 = 0u, k1 = 42u;
    const unsigned k2 = 0x1BD11BDAu ^ k0 ^ k1;
    unsigned x0 = c0 + k0;
    unsigned x1 = c1 + k1;
#define TFR(r) { x0 += x1; x1 = rotl32(x1, (r)); x1 ^= x0; }
    TFR(13) TFR(15) TFR(26) TFR(6)
    x0 += k1; x1 += k2 + 1u;
    TFR(17) TFR(29) TFR(16) TFR(24)
    x0 += k2; x1 += k0 + 2u;
    TFR(13) TFR(15) TFR(26) TFR(6)
    x0 += k0; x1 += k1 + 3u;
    TFR(17) TFR(29) TFR(16) TFR(24)
    x0 += k1; x1 += k2 + 4u;
    TFR(13) TFR(15) TFR(26) TFR(6)
    x0 += k2; x1 += k0 + 5u;
#undef TFR
    o0 = x0; o1 = x1;
}
__device__ __forceinline__ float xla_erfinv32(float x) {
    float w = -log1pf(__fmul_rn(-x, x));
    float p;
    if (w < 5.0f) {
        w = __fadd_rn(w, -2.5f);
        p = 2.81022636e-08f;
        p = __fadd_rn(__fmul_rn(p, w),  3.43273939e-07f);
        p = __fadd_rn(__fmul_rn(p, w), -3.5233877e-06f);
        p = __fadd_rn(__fmul_rn(p, w), -4.39150654e-06f);
        p = __fadd_rn(__fmul_rn(p, w),  0.00021858087f);
        p = __fadd_rn(__fmul_rn(p, w), -0.00125372503f);
        p = __fadd_rn(__fmul_rn(p, w), -0.00417768164f);
        p = __fadd_rn(__fmul_rn(p, w),  0.246640727f);
        p = __fadd_rn(__fmul_rn(p, w),  1.50140941f);
    } else {
        w = __fadd_rn(sqrtf(w), -3.0f);
        p = -0.000200214257f;
        p = __fadd_rn(__fmul_rn(p, w),  0.000100950558f);
        p = __fadd_rn(__fmul_rn(p, w),  0.00134934322f);
        p = __fadd_rn(__fmul_rn(p, w), -0.00367342844f);
        p = __fadd_rn(__fmul_rn(p, w),  0.00573950773f);
        p = __fadd_rn(__fmul_rn(p, w), -0.0076224613f);
        p = __fadd_rn(__fmul_rn(p, w),  0.00943887047f);
        p = __fadd_rn(__fmul_rn(p, w),  1.00167406f);
        p = __fadd_rn(__fmul_rn(p, w),  2.83297682f);
    }
    return __fmul_rn(p, x);
}
__device__ __forceinline__ float jax_normal_eps(unsigned i) {
    unsigned r0, r1;
    threefry2x32_k42(0u, i, r0, r1);
    unsigned bits = r0 ^ r1;
    float f = __fadd_rn(__uint_as_float((bits >> 9) | 0x3f800000u), -1.0f);
    float u = fmaxf(-0.99999994f, __fadd_rn(__fmul_rn(f, 2.0f), -0.99999994f));
    return __fmul_rn(1.41421356237309515f, xla_erfinv32(u));
}

// ---------------------------------------------------------------------------
// coding = mu + eps * exp(0.5*ln_var); psp2 = dual-exp IIR; emit bf16x3 planes
// ---------------------------------------------------------------------------
__global__ __launch_bounds__(256)
void coding_psp2_kernel() {
    int idx = blockIdx.x * blockDim.x + threadIdx.x;   // b*500+f
    if (idx >= B_ * FHID) return;
    int b = idx / FHID;
    int f = idx - b * FHID;
    const float* mu = g_ann + b * (T_ * 1000) + f;      // +1000 per t
    const float* lv = mu + FHID;
    if (f < 12) {
        bf16 z = __float2bfloat16(0.f);
        for (int t = 0; t < T_; t++) {
            int zi = (b * T_ + t) * 512 + FHID + f;
            g_p2p[0][zi] = z; g_p2p[1][zi] = z; g_p2p[2][zi] = z;
        }
    }
    unsigned base = (unsigned)idx * 100u;
    float y1 = 0.f, y2 = 0.f;
    #pragma unroll 4
    for (int t = 0; t < T_; t++) {
        float eps = jax_normal_eps(base + (unsigned)t);
        float sc  = expf(__fmul_rn(0.5f, lv[t * 1000]));
        float cod = __fadd_rn(mu[t * 1000], __fmul_rn(eps, sc));
        float y   = __fadd_rn(__fadd_rn(__fmul_rn(A1F, y1), __fmul_rn(A2F, y2)), cod);
        bf16 b0, b1, b2;
        split3(y, b0, b1, b2);
        int oi = (b * T_ + t) * 512 + f;
        g_p2p[0][oi] = b0;
        g_p2p[1][oi] = b1;
        g_p2p[2][oi] = b2;
        y2 = y1; y1 = y;
    }
}

// ---------------------------------------------------------------------------
// LIF2 + IIR -> g_psp3 [n,500]
// ---------------------------------------------------------------------------
__global__ __launch_bounds__(256)
void lif2_psp3_kernel() {
    int idx = blockIdx.x * blockDim.x + threadIdx.x;
    if (idx >= B_ * FHID) return;
    int b = idx / FHID;
    int f = idx - b * FHID;
    const float* c = g_cur2 + b * (T_ * FHID) + f;
    float* out     = g_psp3 + b * (T_ * FHID) + f;
    float v = 0.f, s = 0.f, y1 = 0.f, y2 = 0.f;
    #pragma unroll 4
    for (int t = 0; t < T_; t++) {
        float vn = __fadd_rn(__fmul_rn(__fmul_rn(v, EMF), __fsub_rn(1.0f, s)), c[t * FHID]);
        float spk = (vn > 1.0f) ? 1.0f : 0.0f;
        v = vn; s = spk;
        float y = __fadd_rn(__fadd_rn(__fmul_rn(A1F, y1), __fmul_rn(A2F, y2)), spk);
        out[t * FHID] = y;
        y2 = y1; y1 = y;
    }
}

// ---------------------------------------------------------------------------
// GEMM3 (fp32, tiny): cur3[n,o] = sum_k W3[o,k]*psp3[n,k] + b3[o]
// ---------------------------------------------------------------------------
__global__ __launch_bounds__(256)
void gemm3_kernel(const float* __restrict__ W3, const float* __restrict__ b3) {
    __shared__ __align__(16) float Ws[FOUT * FHID];
    for (int i = threadIdx.x; i < FOUT * FHID; i += 256) Ws[i] = W3[i];
    __syncthreads();
    int n = blockIdx.x * 256 + threadIdx.x;
    float acc[FOUT];
    #pragma unroll
    for (int o = 0; o < FOUT; o++) acc[o] = 0.f;
    const float4* xp = reinterpret_cast<const float4*>(g_psp3 + n * FHID);
    #pragma unroll 5
    for (int k4 = 0; k4 < FHID / 4; k4++) {
        float4 x = xp[k4];
        #pragma unroll
        for (int o = 0; o < FOUT; o++) {
            float4 w = *reinterpret_cast<const float4*>(&Ws[o * FHID + k4 * 4]);
            acc[o] += w.x * x.x;
            acc[o] += w.y * x.y;
            acc[o] += w.z * x.z;
            acc[o] += w.w * x.w;
        }
    }
    #pragma unroll
    for (int o = 0; o < FOUT; o++)
        g_cur3[n * FOUT + o] = __fadd_rn(acc[o], b3[o]);
}

// ---------------------------------------------------------------------------
// LIF3 -> output spikes [b,o,t]
// ---------------------------------------------------------------------------
__global__ __launch_bounds__(256)
void lif3_kernel(float* __restrict__ out) {
    int idx = blockIdx.x * blockDim.x + threadIdx.x;
    if (idx >= B_ * FOUT) return;
    int b = idx / FOUT;
    int o = idx - b * FOUT;
    const float* c = g_cur3 + b * (T_ * FOUT) + o;
    float* op = out + idx * T_;
    float v = 0.f, s = 0.f;
    #pragma unroll 4
    for (int t = 0; t < T_; t++) {
        float vn = __fadd_rn(__fmul_rn(__fmul_rn(v, EMF), __fsub_rn(1.0f, s)), c[t * FOUT]);
        float spk = (vn > 1.0f) ? 1.0f : 0.0f;
        v = vn; s = spk;
        op[t] = spk;
    }
}

// ---------------------------------------------------------------------------
extern "C" void kernel_launch(void* const* d_in, const int* in_sizes, int n_in,
                              void* d_out, int out_size) {
    const float* inputs = (const float*)d_in[0];
    const float* W1     = (const float*)d_in[1];
    const float* b1     = (const float*)d_in[2];
    const float* W2     = (const float*)d_in[3];
    const float* b2     = (const float*)d_in[4];
    const float* W3     = (const float*)d_in[5];
    const float* b3     = (const float*)d_in[6];
    float* out          = (float*)d_out;

    constexpr int GEMM_SMEM = 122880;
    cudaFuncSetAttribute(gemm_b3<0>, cudaFuncAttributeMaxDynamicSharedMemorySize, GEMM_SMEM);
    cudaFuncSetAttribute(gemm_b3<1>, cudaFuncAttributeMaxDynamicSharedMemorySize, GEMM_SMEM);

    // Prep: split weights + transpose/split inputs
    split_w_kernel<0><<<(1024 * 800 + 255) / 256, 256>>>(W1);
    split_w_kernel<1><<<(512 * 512 + 255) / 256, 256>>>(W2);
    transpose_split_inputs<<<dim3(25, 256), 256>>>(inputs);

    // Layer 1: ann = relu(W1 @ x + b1)
    gemm_b3<0><<<dim3(8, 200), 256, GEMM_SMEM>>>(b1);
    // coding + IIR -> bf16x3 planes
    coding_psp2_kernel<<<(B_ * FHID + 255) / 256, 256>>>();
    // Layer 2 GEMM
    gemm_b3<1><<<dim3(4, 200), 256, GEMM_SMEM>>>(b2);
    // LIF2 + IIR
    lif2_psp3_kernel<<<(B_ * FHID + 255) / 256, 256>>>();
    // Layer 3 GEMM + LIF
    gemm3_kernel<<<NTOK / 256, 256>>>(W3, b3);
    lif3_kernel<<<(B_ * FOUT + 255) / 256, 256>>>(out);
}